// round 10
// baseline (speedup 1.0000x reference)
#include <cuda_runtime.h>

#define BB 256
#define NN 256
#define KNNK 4
#define NPTS (BB*NN)

// ---------------- device scratch (allocation-free requirement) ----------------
__device__ float g_a[NPTS*192];
__device__ float g_b[NPTS*192];
__device__ float g_c[NPTS*192];
__device__ float g_d[NPTS*192];
__device__ float g_h[NPTS*192];
__device__ float g_pool[BB*768];
__device__ int   g_idx[NPTS*KNNK];

// ---------------- helpers ----------------
typedef unsigned long long ull;

__device__ __forceinline__ float leakyf(float x) { return x >= 0.f ? x : 0.01f * x; }

__device__ __forceinline__ ull pack2(float x) {
    ull r; unsigned u = __float_as_uint(x);
    asm("mov.b64 %0, {%1, %1};" : "=l"(r) : "r"(u));
    return r;
}
__device__ __forceinline__ void fma2(ull& d, ull a, ull b) {
    asm("fma.rn.f32x2 %0, %1, %2, %0;" : "+l"(d) : "l"(a), "l"(b));
}
__device__ __forceinline__ ull add2(ull a, ull b) {
    ull r;
    asm("add.rn.f32x2 %0, %1, %2;" : "=l"(r) : "l"(a), "l"(b));
    return r;
}
__device__ __forceinline__ float2 unpack2(ull v) {
    unsigned lo, hi;
    asm("mov.b64 {%0, %1}, %2;" : "=r"(lo), "=r"(hi) : "l"(v));
    return make_float2(__uint_as_float(lo), __uint_as_float(hi));
}

// ---------------- KNN (unchanged) ----------------
__global__ void knn_kernel(const float* __restrict__ pos, int stride, int* __restrict__ idx) {
    __shared__ float sx[NN], sy[NN], sz[NN];
    int b = blockIdx.x, i = threadIdx.x;
    const float* p = pos + ((size_t)b * NN + i) * stride;
    sx[i] = p[0]; sy[i] = p[1]; sz[i] = p[2];
    __syncthreads();
    float xi = sx[i], yi = sy[i], zi = sz[i];
    float d0 = 1e38f, d1 = 1e38f, d2 = 1e38f, d3 = 1e38f;
    int i0 = 0, i1 = 0, i2 = 0, i3 = 0;
    for (int j = 0; j < NN; j++) {
        if (j == i) continue;
        float dx = __fadd_rn(xi, -sx[j]);
        float dy = __fadd_rn(yi, -sy[j]);
        float dz = __fadd_rn(zi, -sz[j]);
        float d = __fmaf_rn(dz, dz, __fmaf_rn(dy, dy, __fmul_rn(dx, dx)));
        if (d < d3) {
            if (d < d2) {
                d3 = d2; i3 = i2;
                if (d < d1) {
                    d2 = d1; i2 = i1;
                    if (d < d0) { d1 = d0; i1 = i0; d0 = d; i0 = j; }
                    else        { d1 = d;  i1 = j; }
                } else { d2 = d; i2 = j; }
            } else { d3 = d; i3 = j; }
        }
    }
    int base = (b * NN + i) * KNNK;
    idx[base] = i0; idx[base + 1] = i1; idx[base + 2] = i2; idx[base + 3] = i3;
}

// ---------------- vectorized-reduction GEMM core: 2 channels x 2 edge-pairs ----------------
// Per-lane (edge,channel) math identical to R7-R9: p_l = sum over k≡l (mod 8),
// q_j = p_j + p_{j+4}, total = ((q0+q1)+(q2+q3)), sequential tail.
__device__ __forceinline__ void addin2(ull a[2], const ull b[2]) {
    a[0] = add2(a[0], b[0]); a[1] = add2(a[1], b[1]);
}
template<int K, int L>
__device__ __forceinline__ void sweep2(ull aA[2], ull aB[2],
                                       const float* __restrict__ w, int H, int cp,
                                       const float* __restrict__ smat) {
    aA[0] = 0; aA[1] = 0; aB[0] = 0; aB[1] = 0;
    constexpr int KMAIN = K & ~7;
    #pragma unroll 4
    for (int k = L; k < KMAIN; k += 8) {
        float2 wv = __ldg((const float2*)(w + (size_t)k * H) + cp);
        ull wA = pack2(wv.x), wB = pack2(wv.y);
        ulonglong2 vv = *(const ulonglong2*)(smat + k * 16);
        fma2(aA[0], vv.x, wA); fma2(aA[1], vv.y, wA);
        fma2(aB[0], vv.x, wB); fma2(aB[1], vv.y, wB);
    }
}
template<int K>
__device__ __forceinline__ void gemm_tree2(ull tA[2], ull tB[2],
                                           const float* __restrict__ w, int H, int cp,
                                           const float* __restrict__ smat) {
    ull TA[2], TB[2], SA[2], SB[2], aA[2], aB[2];
    sweep2<K, 0>(tA, tB, w, H, cp, smat);
    sweep2<K, 4>(aA, aB, w, H, cp, smat); addin2(tA, aA); addin2(tB, aB);   // q0
    sweep2<K, 1>(TA, TB, w, H, cp, smat);
    sweep2<K, 5>(aA, aB, w, H, cp, smat); addin2(TA, aA); addin2(TB, aB);   // q1
    addin2(tA, TA); addin2(tB, TB);                                          // q0+q1
    sweep2<K, 2>(TA, TB, w, H, cp, smat);
    sweep2<K, 6>(aA, aB, w, H, cp, smat); addin2(TA, aA); addin2(TB, aB);   // q2
    sweep2<K, 3>(SA, SB, w, H, cp, smat);
    sweep2<K, 7>(aA, aB, w, H, cp, smat); addin2(SA, aA); addin2(SB, aB);   // q3
    addin2(TA, SA); addin2(TB, SB);                                          // q2+q3
    addin2(tA, TA); addin2(tB, TB);
    constexpr int KMAIN = K & ~7;
    #pragma unroll
    for (int k = KMAIN; k < K; k++) {                                        // scalar tail
        float2 wv = __ldg((const float2*)(w + (size_t)k * H) + cp);
        ull wA = pack2(wv.x), wB = pack2(wv.y);
        ulonglong2 vv = *(const ulonglong2*)(smat + k * 16);
        fma2(tA[0], vv.x, wA); fma2(tA[1], vv.y, wA);
        fma2(tB[0], vv.x, wB); fma2(tB[1], vv.y, wB);
    }
}

// ---------------- fused EdgeConv: 4 points (16 edges)/block, 512 threads ----------------
// thread = (channel-pair cp, quarter q): channels (2cp,2cp+1) x edges (4q..4q+3).
template<int FIN, int H>
__global__ void __launch_bounds__(512, 2)
edgeconv_kernel(const float* __restrict__ feat,
                const int* __restrict__ idx,
                const float* __restrict__ w1, const float* __restrict__ b1,
                const float* __restrict__ w2, const float* __restrict__ b2,
                float* __restrict__ out) {
    constexpr int Cout = 192;
    constexpr int F2 = 2 * FIN;
    __shared__ __align__(16) float sf[F2 * 16];   // [k*16 + e]
    __shared__ __align__(16) float s[252 * 16];   // [j*16 + e]
    __shared__ int nb[16];

    int m0 = blockIdx.x * 4;
    int tid = threadIdx.x;

    if (tid < 16) {
        int p = tid >> 2;
        int m = m0 + p;
        nb[tid] = (m & ~(NN - 1)) + idx[m * KNNK + (tid & 3)];
    }
    __syncthreads();

    // build edge features: e = [xi, rn(xj - xi)]
    #pragma unroll 2
    for (int t = tid; t < F2 * 16; t += 512) {
        int e = t & 15, k = t >> 4;
        int p = e >> 2;
        float v;
        if (k < FIN) {
            v = feat[(size_t)(m0 + p) * FIN + k];
        } else {
            int kk = k - FIN;
            v = __fadd_rn(feat[(size_t)nb[e] * FIN + kk], -feat[(size_t)(m0 + p) * FIN + kk]);
        }
        sf[t] = v;
    }
    __syncthreads();

    int cp = tid >> 2, q = tid & 3;

    // GEMM 1: s = leaky(e @ w1 + b1)
    if (cp < H / 2) {
        ull tA[2], tB[2];
        gemm_tree2<F2>(tA, tB, w1, H, cp, sf + 4 * q);
        int j0 = 2 * cp;
        float bA = b1[j0], bB = b1[j0 + 1];
        float2 a0 = unpack2(tA[0]), a1 = unpack2(tA[1]);
        float2 c0 = unpack2(tB[0]), c1 = unpack2(tB[1]);
        float4 oA = make_float4(leakyf(__fadd_rn(a0.x, bA)), leakyf(__fadd_rn(a0.y, bA)),
                                leakyf(__fadd_rn(a1.x, bA)), leakyf(__fadd_rn(a1.y, bA)));
        float4 oB = make_float4(leakyf(__fadd_rn(c0.x, bB)), leakyf(__fadd_rn(c0.y, bB)),
                                leakyf(__fadd_rn(c1.x, bB)), leakyf(__fadd_rn(c1.y, bB)));
        *(float4*)(s + j0 * 16 + 4 * q)       = oA;
        *(float4*)(s + (j0 + 1) * 16 + 4 * q) = oB;
    }
    __syncthreads();

    // GEMM 2 + leaky + sum over 4 edges; quarter q == point q
    if (cp < Cout / 2) {
        ull tA[2], tB[2];
        gemm_tree2<H>(tA, tB, w2, Cout, cp, s + 4 * q);
        int o0 = 2 * cp;
        float bA = b2[o0], bB = b2[o0 + 1];
        float2 a0 = unpack2(tA[0]), a1 = unpack2(tA[1]);
        float2 c0 = unpack2(tB[0]), c1 = unpack2(tB[1]);
        float rA = leakyf(a0.x + bA) + leakyf(a0.y + bA) +
                   leakyf(a1.x + bA) + leakyf(a1.y + bA);
        float rB = leakyf(c0.x + bB) + leakyf(c0.y + bB) +
                   leakyf(c1.x + bB) + leakyf(c1.y + bB);
        *(float2*)(out + (size_t)(m0 + q) * Cout + o0) = make_float2(rA, rB);
    }
}

// ---------------- nn1+nn2 fused: 8 points/block, 256 threads, 2ch x 4pt threads ----------------
__global__ void nn12_kernel(const float* __restrict__ x,
                            const float* __restrict__ a, const float* __restrict__ b,
                            const float* __restrict__ c, const float* __restrict__ d,
                            const float* __restrict__ w1, const float* __restrict__ b1,
                            const float* __restrict__ w2, const float* __restrict__ b2,
                            float* __restrict__ hout) {
    __shared__ __align__(16) float sin_[772 * 8];
    __shared__ __align__(16) float sh1[252 * 8];
    int m0 = blockIdx.x * 8;
    int tid = threadIdx.x;
    for (int e = tid; e < 772 * 8; e += blockDim.x) {
        int ch = e >> 3, p = e & 7;
        size_t mp = (size_t)(m0 + p);
        float val;
        if (ch < 4)        val = x[mp * 4 + ch];
        else if (ch < 196) val = a[mp * 192 + (ch - 4)];
        else if (ch < 388) val = b[mp * 192 + (ch - 196)];
        else if (ch < 580) val = c[mp * 192 + (ch - 388)];
        else               val = d[mp * 192 + (ch - 580)];
        sin_[e] = val;
    }
    __syncthreads();
    int cp = tid >> 1, h = tid & 1;   // half h owns points 4h..4h+3
    if (cp < 126) {
        ull aA[2] = {0, 0}, aB[2] = {0, 0};
        #pragma unroll 4
        for (int k = 0; k < 772; k++) {
            float2 wv = __ldg((const float2*)(w1 + (size_t)k * 252) + cp);
            ull wA = pack2(wv.x), wB = pack2(wv.y);
            ulonglong2 vv = *(const ulonglong2*)(sin_ + k * 8 + 4 * h);
            fma2(aA[0], vv.x, wA); fma2(aA[1], vv.y, wA);
            fma2(aB[0], vv.x, wB); fma2(aB[1], vv.y, wB);
        }
        int j0 = 2 * cp;
        float bA = b1[j0], bB = b1[j0 + 1];
        float2 r0 = unpack2(aA[0]), r1 = unpack2(aA[1]);
        float2 s0 = unpack2(aB[0]), s1 = unpack2(aB[1]);
        *(float4*)(sh1 + j0 * 8 + 4 * h) =
            make_float4(leakyf(r0.x + bA), leakyf(r0.y + bA),
                        leakyf(r1.x + bA), leakyf(r1.y + bA));
        *(float4*)(sh1 + (j0 + 1) * 8 + 4 * h) =
            make_float4(leakyf(s0.x + bB), leakyf(s0.y + bB),
                        leakyf(s1.x + bB), leakyf(s1.y + bB));
    }
    __syncthreads();
    if (cp < 96) {
        ull aA[2] = {0, 0}, aB[2] = {0, 0};
        #pragma unroll 4
        for (int mm = 0; mm < 252; mm++) {
            float2 wv = __ldg((const float2*)(w2 + mm * 192) + cp);
            ull wA = pack2(wv.x), wB = pack2(wv.y);
            ulonglong2 vv = *(const ulonglong2*)(sh1 + mm * 8 + 4 * h);
            fma2(aA[0], vv.x, wA); fma2(aA[1], vv.y, wA);
            fma2(aB[0], vv.x, wB); fma2(aB[1], vv.y, wB);
        }
        int o0 = 2 * cp;
        float bA = b2[o0], bB = b2[o0 + 1];
        float2 r0 = unpack2(aA[0]), r1 = unpack2(aA[1]);   // points 4h,4h+1 / 4h+2,4h+3 (ch A)
        float2 s0 = unpack2(aB[0]), s1 = unpack2(aB[1]);   // same points (ch B)
        *(float2*)(hout + (size_t)(m0 + 4 * h + 0) * 192 + o0) = make_float2(r0.x + bA, s0.x + bB);
        *(float2*)(hout + (size_t)(m0 + 4 * h + 1) * 192 + o0) = make_float2(r0.y + bA, s0.y + bB);
        *(float2*)(hout + (size_t)(m0 + 4 * h + 2) * 192 + o0) = make_float2(r1.x + bA, s1.x + bB);
        *(float2*)(hout + (size_t)(m0 + 4 * h + 3) * 192 + o0) = make_float2(r1.y + bA, s1.y + bB);
    }
}

// ---------------- pooling (unchanged) ----------------
__global__ void pool_kernel(const float* __restrict__ h, float* __restrict__ pooled) {
    int b = blockIdx.x, cch = threadIdx.x;
    const float* hp = h + (size_t)b * NN * 192 + cch;
    float mx = -1e38f, mn = 1e38f;
    double sm = 0.0;
    #pragma unroll 4
    for (int n = 0; n < NN; n++) {
        float v = hp[(size_t)n * 192];
        mx = fmaxf(mx, v); mn = fminf(mn, v);
        sm += (double)v;
    }
    float smf = (float)sm;
    float* pb = pooled + b * 768;
    pb[cch]       = leakyf(mx);
    pb[192 + cch] = leakyf(mn);
    pb[384 + cch] = leakyf(smf);
    pb[576 + cch] = leakyf(__fmul_rn(smf, (1.0f / 256.0f)));
}

// ---------------- final head (unchanged) ----------------
__global__ void final_kernel(const float* __restrict__ pooled,
                             const float* __restrict__ w3, const float* __restrict__ b3,
                             const float* __restrict__ w4, const float* __restrict__ b4,
                             float* __restrict__ out) {
    __shared__ float sp[768];
    __shared__ float smid[96];
    int b = blockIdx.x, tid = threadIdx.x;
    for (int e = tid; e < 768; e += blockDim.x) sp[e] = pooled[b * 768 + e];
    __syncthreads();
    if (tid < 96) {
        float acc = 0.f;
        for (int k = 0; k < 768; k++) acc = fmaf(sp[k], w3[k * 96 + tid], acc);
        smid[tid] = leakyf(acc + b3[tid]);
    }
    __syncthreads();
    if (tid == 0) {
        float sacc = 0.f;
        for (int k = 0; k < 96; k++) sacc = fmaf(smid[k], w4[k], sacc);
        out[b] = sacc + b4[0];
    }
}

// ---------------- launch ----------------
extern "C" void kernel_launch(void* const* d_in, const int* in_sizes, int n_in,
                              void* d_out, int out_size) {
    const float* x = (const float*)d_in[0];
    const float* prm[24];
    for (int i = 0; i < 24; i++) prm[i] = (const float*)d_in[i + 1];

    float *ga, *gb, *gc, *gd, *gh, *gp;
    int* gi;
    cudaGetSymbolAddress((void**)&ga, g_a);
    cudaGetSymbolAddress((void**)&gb, g_b);
    cudaGetSymbolAddress((void**)&gc, g_c);
    cudaGetSymbolAddress((void**)&gd, g_d);
    cudaGetSymbolAddress((void**)&gh, g_h);
    cudaGetSymbolAddress((void**)&gp, g_pool);
    cudaGetSymbolAddress((void**)&gi, g_idx);

    knn_kernel<<<BB, NN>>>(x, 4, gi);
    edgeconv_kernel<4, 96><<<NPTS / 4, 512>>>(x, gi, prm[0], prm[1], prm[2], prm[3], ga);

    knn_kernel<<<BB, NN>>>(ga, 192, gi);
    edgeconv_kernel<192, 252><<<NPTS / 4, 512>>>(ga, gi, prm[4], prm[5], prm[6], prm[7], gb);

    knn_kernel<<<BB, NN>>>(gb, 192, gi);
    edgeconv_kernel<192, 252><<<NPTS / 4, 512>>>(gb, gi, prm[8], prm[9], prm[10], prm[11], gc);

    knn_kernel<<<BB, NN>>>(gc, 192, gi);
    edgeconv_kernel<192, 252><<<NPTS / 4, 512>>>(gc, gi, prm[12], prm[13], prm[14], prm[15], gd);

    nn12_kernel<<<NPTS / 8, 256>>>(x, ga, gb, gc, gd,
                                   prm[16], prm[17], prm[18], prm[19], gh);

    pool_kernel<<<BB, 192>>>(gh, gp);
    final_kernel<<<BB, 128>>>(gp, prm[20], prm[21], prm[22], prm[23], (float*)d_out);
}